// round 15
// baseline (speedup 1.0000x reference)
#include <cuda_runtime.h>
#include <cuda_fp16.h>
#include <cstddef>

// Fixed shapes
#define T_STEPS 336
#define NT      256          // 8 warps, 2 per SMSP
#define NCTAS   128          // 8 batch elems per CTA

typedef unsigned long long u64;

// ---- shared memory layout ----
// fp16 weight region (offsets in HALFS). Per k-pair row (stride WH=520 halfs):
//   j*8 + gate*2 + ki : gates i,f,g,o; ki = k within pair.
//   Rows interleaved by split-K half: row = local_pair*2 + kpar.
#define WH       520
#define HOFF_W0X 0            // K=16  -> 8 rows
#define HOFF_W0H 4160         // K=64  -> 32 rows
#define HOFF_W1X 20800
#define HOFF_W1H 37440
// float region (offsets in FLOATS; starts at half-offset 54080 = float 27040)
#define OFF_B   27040         // 512: combined biases, [layer*256 + gate*64 + j]
#define OFF_X   27552         // 2 bufs x (8 elems x 20)
#define OFF_H0  27872         // 2 bufs x (8 elems x 68), k-swizzled pos(k)=k+(k>=32)*4
#define OFF_H1  28960         // 2 bufs x 544
#define SMEM_FLOATS 30048
#define SMEM_BYTES (SMEM_FLOATS * 4)   // 120,192 B

// group-local barrier: 128 threads of one eg-group
#define BARG(id) asm volatile("bar.sync %0, %1;" :: "r"(id), "r"(128) : "memory")

// ---- packed helpers ----
__device__ __forceinline__ u64 fma2(u64 a, u64 b, u64 c) {
    u64 d;
    asm("fma.rn.f32x2 %0, %1, %2, %3;" : "=l"(d) : "l"(a), "l"(b), "l"(c));
    return d;
}
__device__ __forceinline__ ulonglong2 lds2(const float* p) {
    return *reinterpret_cast<const ulonglong2*>(p);
}
__device__ __forceinline__ float foldadd(u64 v) {
    float lo, hi;
    asm("mov.b64 {%0,%1}, %2;" : "=f"(lo), "=f"(hi) : "l"(v));
    return lo + hi;
}
// fp16x2 (as uint) -> packed f32x2 in u64
__device__ __forceinline__ u64 h2tof2(unsigned v) {
    const __half2 h = *reinterpret_cast<const __half2*>(&v);
    const float2 f = __half22float2(h);
    u64 r;
    asm("mov.b64 %0, {%1, %2};" : "=l"(r) : "f"(f.x), "f"(f.y));
    return r;
}
__device__ __forceinline__ float sigf(float x) {
    return __fdividef(1.0f, 1.0f + __expf(-x));
}
__device__ __forceinline__ float tanhe(float x) {
    return 1.0f - __fdividef(2.0f, __expf(2.0f * x) + 1.0f);
}

// GEMM over NCH chunks of 4 k (= 2 k-pairs). acc[gate*4+e], gates i,f,g,o.
// wbase: fp16 segment + kp*WH + j*8 baked in. hbase: fp32 buf + e0*HS + kp-offset baked in.
template<int NCH, int HS>
__device__ __forceinline__ void gemm2h(u64* __restrict__ acc,
                                       const __half* __restrict__ wbase,
                                       const float* __restrict__ hbase)
{
#pragma unroll
    for (int c = 0; c < NCH; ++c) {
        ulonglong2 hv0 = lds2(hbase + 0 * HS + c * 4);
        ulonglong2 hv1 = lds2(hbase + 1 * HS + c * 4);
        ulonglong2 hv2 = lds2(hbase + 2 * HS + c * 4);
        ulonglong2 hv3 = lds2(hbase + 3 * HS + c * 4);
#pragma unroll
        for (int ki2 = 0; ki2 < 2; ++ki2) {
            const uint4 w = *reinterpret_cast<const uint4*>(
                wbase + (size_t)(4 * c + 2 * ki2) * WH);
            const u64 wi = h2tof2(w.x);
            const u64 wf = h2tof2(w.y);
            const u64 wg = h2tof2(w.z);
            const u64 wo = h2tof2(w.w);
            const u64 h0 = ki2 ? hv0.y : hv0.x;
            const u64 h1 = ki2 ? hv1.y : hv1.x;
            const u64 h2 = ki2 ? hv2.y : hv2.x;
            const u64 h3 = ki2 ? hv3.y : hv3.x;
            acc[0]  = fma2(wi, h0, acc[0]);
            acc[1]  = fma2(wi, h1, acc[1]);
            acc[2]  = fma2(wi, h2, acc[2]);
            acc[3]  = fma2(wi, h3, acc[3]);
            acc[4]  = fma2(wf, h0, acc[4]);
            acc[5]  = fma2(wf, h1, acc[5]);
            acc[6]  = fma2(wf, h2, acc[6]);
            acc[7]  = fma2(wf, h3, acc[7]);
            acc[8]  = fma2(wg, h0, acc[8]);
            acc[9]  = fma2(wg, h1, acc[9]);
            acc[10] = fma2(wg, h2, acc[10]);
            acc[11] = fma2(wg, h3, acc[11]);
            acc[12] = fma2(wo, h0, acc[12]);
            acc[13] = fma2(wo, h1, acc[13]);
            acc[14] = fma2(wo, h2, acc[14]);
            acc[15] = fma2(wo, h3, acc[15]);
        }
    }
}

__device__ __forceinline__ void combine16(u64* __restrict__ acc, float* __restrict__ s) {
#pragma unroll
    for (int i = 0; i < 16; ++i) s[i] = foldadd(acc[i]);
#pragma unroll
    for (int i = 0; i < 16; ++i) s[i] += __shfl_xor_sync(0xffffffffu, s[i], 16);
}

// Split activation: kp0 lanes finalize elems {0,1}, kp1 lanes elems {2,3} of the quartet.
__device__ __forceinline__ void act2sel(const float* __restrict__ s, int kp,
                                        float bi, float bf, float bg, float bo,
                                        float* __restrict__ c, float* __restrict__ hw)
{
#pragma unroll
    for (int q = 0; q < 2; ++q) {
        const float si = kp ? s[2 + q]  : s[q];
        const float sf = kp ? s[6 + q]  : s[4 + q];
        const float sg = kp ? s[10 + q] : s[8 + q];
        const float so = kp ? s[14 + q] : s[12 + q];
        const float gi = sigf(si + bi);
        const float gf = sigf(sf + bf);
        const float gg = tanhe(sg + bg);
        const float go = sigf(so + bo);
        c[q] = fmaf(gf, c[q], gi * gg);
        hw[(2 * kp + q) * 68] = go * tanhe(c[q]);
    }
}

__global__ void __launch_bounds__(NT, 1)
lstm2_kernel(const float* __restrict__ x,
             const float* __restrict__ Wih0, const float* __restrict__ Whh0,
             const float* __restrict__ bih0, const float* __restrict__ bhh0,
             const float* __restrict__ Wih1, const float* __restrict__ Whh1,
             const float* __restrict__ bih1, const float* __restrict__ bhh1,
             const float* __restrict__ Wfc,  const float* __restrict__ bfc,
             float* __restrict__ out)
{
    extern __shared__ float sh[];
    __half* const shh = reinterpret_cast<__half*>(sh);
    const int tid = threadIdx.x;

    // ---- stage weights as fp16 in k-pair-packed layout ----
    for (int idx = tid; idx < 256 * 16; idx += NT) {
        const int gr = idx >> 4, k = idx & 15;
        const int g = gr >> 6, j = gr & 63;
        const int p2 = k >> 1;
        const int kh = (p2 >= 4) ? 1 : 0;
        const int row = (p2 - kh * 4) * 2 + kh;
        shh[HOFF_W0X + row * WH + j * 8 + g * 2 + (k & 1)] = __float2half(Wih0[idx]);
    }
    for (int idx = tid; idx < 256 * 64; idx += NT) {
        const int gr = idx >> 6, k = idx & 63;
        const int g = gr >> 6, j = gr & 63;
        const int p2 = k >> 1;
        const int kh = (p2 >= 16) ? 1 : 0;
        const int row = (p2 - kh * 16) * 2 + kh;
        const int o = row * WH + j * 8 + g * 2 + (k & 1);
        shh[HOFF_W0H + o] = __float2half(Whh0[idx]);
        shh[HOFF_W1X + o] = __float2half(Wih1[idx]);
        shh[HOFF_W1H + o] = __float2half(Whh1[idx]);
    }
    if (tid < 256) {
        sh[OFF_B + tid]       = bih0[tid] + bhh0[tid];
        sh[OFF_B + 256 + tid] = bih1[tid] + bhh1[tid];
    }
    for (int idx = tid; idx < 2176; idx += NT) sh[OFF_H0 + idx] = 0.0f;

    // ---- thread mapping: warp=(eg,jq); lane=(kp,hl) ----
    const int wid = tid >> 5, lane = tid & 31;
    const int eg  = wid >> 2;
    const int jq  = wid & 3;
    const int hl  = lane & 15;
    const int kp  = lane >> 4;
    const int j   = jq * 16 + hl;
    const int e0  = eg * 4;
    const int gid = eg + 1;              // named barrier id for this group

    // x staging owned by kp==1 lanes: pid 0..127 -> (elem, k)
    const int pid = wid * 16 + hl;
    const int xe = pid >> 4, xk = pid & 15;
    const float* xptr = x + ((size_t)(blockIdx.x * 8 + xe) * T_STEPS) * 16 + xk;
    float xreg = 0.0f;
    if (kp == 1) {
        sh[OFF_X + xe * 20 + xk] = xptr[0];   // x(0) -> buf 0
        xreg = xptr[16];                      // prefetch x(1)
    }
    __syncthreads();

    const float b0i = sh[OFF_B +   0 + j], b0f = sh[OFF_B +  64 + j];
    const float b0g = sh[OFF_B + 128 + j], b0o = sh[OFF_B + 192 + j];
    const float b1i = sh[OFF_B + 256 + j], b1f = sh[OFF_B + 320 + j];
    const float b1g = sh[OFF_B + 384 + j], b1o = sh[OFF_B + 448 + j];

    const __half* w0x = &shh[HOFF_W0X + kp * WH + j * 8];
    const __half* w0h = &shh[HOFF_W0H + kp * WH + j * 8];
    const __half* w1x = &shh[HOFF_W1X + kp * WH + j * 8];
    const __half* w1h = &shh[HOFF_W1H + kp * WH + j * 8];
    const int hko = kp * 36;             // swizzled k-offset for this K-half
    const int pj  = j + ((j >> 5) << 2); // swizzled j for h stores
    float c0[2] = {0.f, 0.f};
    float c1[2] = {0.f, 0.f};
    float s[16];

    // ================= Prologue: L0(0) =================
    {
        u64 acc[16];
#pragma unroll
        for (int i = 0; i < 16; ++i) acc[i] = 0ull;
        gemm2h<2, 20>(acc, w0x, &sh[OFF_X + 0 * 160 + e0 * 20 + kp * 8]);   // x(0) buf0
        gemm2h<8, 68>(acc, w0h, &sh[OFF_H0 + 1 * 544 + e0 * 68 + hko]);     // zeros buf1
        combine16(acc, s);
        act2sel(s, kp, b0i, b0f, b0g, b0o, c0,
                &sh[OFF_H0 + 0 * 544 + e0 * 68 + pj]);                      // h0(0)->buf0
        if (kp == 1) {
            sh[OFF_X + 1 * 160 + xe * 20 + xk] = xreg;       // x(1) -> buf1
            xreg = xptr[2 * 16];                             // prefetch x(2)
        }
    }

    // ================= Main windows w = 0..334: L1(w) + L0(w+1) =================
    int p = 0;   // p = w & 1
    for (int w = 0; w < T_STEPS - 1; ++w) {
        BARG(gid);   // group-local: h0(w)@p, h1(w-1)@1-p, x(w+1)@1-p visible

        u64 accA[16], accB[16];
#pragma unroll
        for (int i = 0; i < 16; ++i) { accA[i] = 0ull; accB[i] = 0ull; }

        // L1(w): reads h0(w)@p, h1(w-1)@1-p
        gemm2h<8, 68>(accA, w1x, &sh[OFF_H0 + p * 544 + e0 * 68 + hko]);
        gemm2h<8, 68>(accA, w1h, &sh[OFF_H1 + (1 - p) * 544 + e0 * 68 + hko]);
        // L0(w+1): reads x(w+1)@1-p, h0(w)@p
        gemm2h<2, 20>(accB, w0x, &sh[OFF_X + (1 - p) * 160 + e0 * 20 + kp * 8]);
        gemm2h<8, 68>(accB, w0h, &sh[OFF_H0 + p * 544 + e0 * 68 + hko]);

        combine16(accA, s);
        act2sel(s, kp, b1i, b1f, b1g, b1o, c1,
                &sh[OFF_H1 + p * 544 + e0 * 68 + pj]);                     // h1(w)->@p
        if (kp == 1) {
            if (w + 2 < T_STEPS)
                sh[OFF_X + p * 160 + xe * 20 + xk] = xreg;   // x(w+2) -> @p
            if (w + 3 < T_STEPS)
                xreg = xptr[(size_t)(w + 3) * 16];
        }
        combine16(accB, s);
        act2sel(s, kp, b0i, b0f, b0g, b0o, c0,
                &sh[OFF_H0 + (1 - p) * 544 + e0 * 68 + pj]);               // h0(w+1)->@1-p
        p ^= 1;
    }

    // ================= Epilogue: L1(335) =================  (p == 1 here)
    BARG(gid);
    {
        u64 acc[16];
#pragma unroll
        for (int i = 0; i < 16; ++i) acc[i] = 0ull;
        gemm2h<8, 68>(acc, w1x, &sh[OFF_H0 + 1 * 544 + e0 * 68 + hko]);   // h0(335)@1
        gemm2h<8, 68>(acc, w1h, &sh[OFF_H1 + 0 * 544 + e0 * 68 + hko]);   // h1(334)@0
        combine16(acc, s);
        act2sel(s, kp, b1i, b1f, b1g, b1o, c1,
                &sh[OFF_H1 + 1 * 544 + e0 * 68 + pj]);                    // h1(335)->@1
    }
    __syncthreads();   // join both groups before FC head

    // ---- FC head: out[b] = dot(Wfc, h1_last[b]) + bfc ---- (h1(335) in buf 1)
    if (tid < 8) {
        const float* hv = &sh[OFF_H1 + 1 * 544 + tid * 68];
        float sum = 0.0f;
#pragma unroll 8
        for (int k = 0; k < 64; ++k) sum += Wfc[k] * hv[k + ((k >> 5) << 2)];
        out[blockIdx.x * 8 + tid] = sum + bfc[0];
    }
}

extern "C" void kernel_launch(void* const* d_in, const int* in_sizes, int n_in,
                              void* d_out, int out_size)
{
    const float* x    = (const float*)d_in[0];
    const float* Wih0 = (const float*)d_in[1];
    const float* Whh0 = (const float*)d_in[2];
    const float* bih0 = (const float*)d_in[3];
    const float* bhh0 = (const float*)d_in[4];
    const float* Wih1 = (const float*)d_in[5];
    const float* Whh1 = (const float*)d_in[6];
    const float* bih1 = (const float*)d_in[7];
    const float* bhh1 = (const float*)d_in[8];
    const float* Wfc  = (const float*)d_in[9];
    const float* bfc  = (const float*)d_in[10];
    float* out = (float*)d_out;

    cudaFuncSetAttribute(lstm2_kernel,
                         cudaFuncAttributeMaxDynamicSharedMemorySize, SMEM_BYTES);
    lstm2_kernel<<<NCTAS, NT, SMEM_BYTES>>>(
        x, Wih0, Whh0, bih0, bhh0, Wih1, Whh1, bih1, bhh1, Wfc, bfc, out);
}